// round 6
// baseline (speedup 1.0000x reference)
#include <cuda_runtime.h>

// SpanIndexEncoder: out[t,f] = sum over nodes n (n < num_nodes, start_n <= t <= end_n) of emb[n,f]
// Event formulation: valid node n emits +emb[n] at row start_n, -emb[n] at row end_n+1.
// Per-chunk (8-row) event lists -> chunk sums -> parallel chunk-prefix scan -> register replay.
// Float4 vectorization: one thread owns 4 features -> event decode/load amortized 4x.
//   T = 8192 tokens, N = 8192 max nodes, F = 256 features.

#define T_MAX  8192
#define N_MAX  8192
#define FDIM   256
#define F4     (FDIM / 4)        // 64 float4 lanes
#define CHUNK  8
#define NCHUNK (T_MAX / CHUNK)   // 1024
#define CAP    512               // events per chunk (actual max ~45 for this data)

// Scratch (allocation-free). g_cnt starts zero (module load) and is cleared by
// k_out each call (consume-and-clear) -> deterministic across graph replays.
__device__ int   g_cnt[NCHUNK];
__device__ int   g_ev[NCHUNK * CAP];     // packed: (n << 4) | (t_local << 1) | neg
__device__ float g_St[FDIM * NCHUNK];    // chunk sums, TRANSPOSED [f][c]
__device__ float g_Pt[FDIM * NCHUNK];    // exclusive chunk prefix, TRANSPOSED [f][c]

// ---------------------------------------------------------------------------
// K1: bin events by chunk. ~9K small atomics on 1024 counters.
// ---------------------------------------------------------------------------
__global__ void k_ev(const int* __restrict__ starts,
                     const int* __restrict__ ends,
                     const int* __restrict__ num_nodes_p) {
    int n = blockIdx.x * blockDim.x + threadIdx.x;
    if (n >= *num_nodes_p) return;
    int s = starts[n];
    int e = ends[n];
    if (s > e) return;                        // empty span
    {   // +emb[n] at row s
        int c = s >> 3, t = s & 7;
        int pos = atomicAdd(&g_cnt[c], 1);
        if (pos < CAP) g_ev[c * CAP + pos] = (n << 4) | (t << 1);
    }
    int e1 = e + 1;
    if (e1 < T_MAX) {                         // -emb[n] at row e+1
        int c = e1 >> 3, t = e1 & 7;
        int pos = atomicAdd(&g_cnt[c], 1);
        if (pos < CAP) g_ev[c * CAP + pos] = (n << 4) | (t << 1) | 1;
    }
}

// ---------------------------------------------------------------------------
// K2: chunk sums from events. Block c (grid=1024), thread f4 owns 4 features.
//   St[f][c] = sum over events in chunk c of (+/-) emb[n][f]
// LDG.128 per event per thread, 4-wide batching for MLP. FFMA with s=+-1.
// Stores to [f][c] layout are strided (fire-and-forget, hidden).
// ---------------------------------------------------------------------------
__global__ void k_S(const float4* __restrict__ emb4) {
    int c  = blockIdx.x;
    int f4 = threadIdx.x;
    int nev = g_cnt[c];
    if (nev > CAP) nev = CAP;
    const int* evp = g_ev + c * CAP;

    float4 a0 = make_float4(0.f, 0.f, 0.f, 0.f), a1 = a0, a2 = a0, a3 = a0;
    int j = 0;
    for (; j + 4 <= nev; j += 4) {
        int e0 = evp[j], e1 = evp[j + 1], e2 = evp[j + 2], e3 = evp[j + 3];
        float4 v0 = emb4[(e0 >> 4) * F4 + f4];
        float4 v1 = emb4[(e1 >> 4) * F4 + f4];
        float4 v2 = emb4[(e2 >> 4) * F4 + f4];
        float4 v3 = emb4[(e3 >> 4) * F4 + f4];
        float s0 = 1.f - 2.f * (float)(e0 & 1);
        float s1 = 1.f - 2.f * (float)(e1 & 1);
        float s2 = 1.f - 2.f * (float)(e2 & 1);
        float s3 = 1.f - 2.f * (float)(e3 & 1);
        a0.x += s0 * v0.x; a0.y += s0 * v0.y; a0.z += s0 * v0.z; a0.w += s0 * v0.w;
        a1.x += s1 * v1.x; a1.y += s1 * v1.y; a1.z += s1 * v1.z; a1.w += s1 * v1.w;
        a2.x += s2 * v2.x; a2.y += s2 * v2.y; a2.z += s2 * v2.z; a2.w += s2 * v2.w;
        a3.x += s3 * v3.x; a3.y += s3 * v3.y; a3.z += s3 * v3.z; a3.w += s3 * v3.w;
    }
    for (; j < nev; j++) {
        int e0 = evp[j];
        float4 v0 = emb4[(e0 >> 4) * F4 + f4];
        float s0 = 1.f - 2.f * (float)(e0 & 1);
        a0.x += s0 * v0.x; a0.y += s0 * v0.y; a0.z += s0 * v0.z; a0.w += s0 * v0.w;
    }
    float rx = (a0.x + a1.x) + (a2.x + a3.x);
    float ry = (a0.y + a1.y) + (a2.y + a3.y);
    float rz = (a0.z + a1.z) + (a2.z + a3.z);
    float rw = (a0.w + a1.w) + (a2.w + a3.w);
    int f = f4 * 4;
    g_St[(f + 0) * NCHUNK + c] = rx;
    g_St[(f + 1) * NCHUNK + c] = ry;
    g_St[(f + 2) * NCHUNK + c] = rz;
    g_St[(f + 3) * NCHUNK + c] = rw;
}

// ---------------------------------------------------------------------------
// K3: parallel exclusive prefix over 1024 chunks, per feature.
// Block f (grid=256), thread c (block=1024, 32 warps). Coalesced load AND
// store ([f][c] layout). Shuffle scan + smem warp-sum combine.
// ---------------------------------------------------------------------------
__global__ void k_scan() {
    int f    = blockIdx.x;
    int c    = threadIdx.x;
    int lane = c & 31;
    int wid  = c >> 5;

    float v = g_St[f * NCHUNK + c];

    float x = v;
#pragma unroll
    for (int d = 1; d < 32; d <<= 1) {
        float u = __shfl_up_sync(0xFFFFFFFFu, x, d);
        if (lane >= d) x += u;
    }

    __shared__ float wsum[32];
    if (lane == 31) wsum[wid] = x;
    __syncthreads();

    if (wid == 0) {
        float y = wsum[lane];
#pragma unroll
        for (int d = 1; d < 32; d <<= 1) {
            float u = __shfl_up_sync(0xFFFFFFFFu, y, d);
            if (lane >= d) y += u;
        }
        wsum[lane] = y;
    }
    __syncthreads();

    float offset = (wid > 0) ? wsum[wid - 1] : 0.f;
    g_Pt[f * NCHUNK + c] = (x + offset) - v;  // exclusive prefix, coalesced store
}

// ---------------------------------------------------------------------------
// K4: output. Block c (grid=1024), thread f4 owns 4 features. Register replay
// into 8 float4 row accumulators (predicated FFMA, no smem RMW), 4-wide load
// batching, then 8-row inclusive scan + coalesced ST.128 stores.
// ---------------------------------------------------------------------------
__global__ void k_out(const float4* __restrict__ emb4, float4* __restrict__ out4) {
    __shared__ int sev[CAP];

    int c  = blockIdx.x;
    int f4 = threadIdx.x;
    int nev = g_cnt[c];
    if (nev > CAP) nev = CAP;

    for (int i = f4; i < nev; i += F4) sev[i] = g_ev[c * CAP + i];
    __syncthreads();
    if (f4 == 0) g_cnt[c] = 0;                // reset for next replay

    float4 r[CHUNK];
#pragma unroll
    for (int t = 0; t < CHUNK; t++) r[t] = make_float4(0.f, 0.f, 0.f, 0.f);

    int j = 0;
    for (; j + 4 <= nev; j += 4) {
        int e0 = sev[j], e1 = sev[j + 1], e2 = sev[j + 2], e3 = sev[j + 3];
        float4 v0 = emb4[(e0 >> 4) * F4 + f4];
        float4 v1 = emb4[(e1 >> 4) * F4 + f4];
        float4 v2 = emb4[(e2 >> 4) * F4 + f4];
        float4 v3 = emb4[(e3 >> 4) * F4 + f4];
        float s0 = 1.f - 2.f * (float)(e0 & 1);
        float s1 = 1.f - 2.f * (float)(e1 & 1);
        float s2 = 1.f - 2.f * (float)(e2 & 1);
        float s3 = 1.f - 2.f * (float)(e3 & 1);
        int t0 = (e0 >> 1) & 7, t1 = (e1 >> 1) & 7;
        int t2 = (e2 >> 1) & 7, t3 = (e3 >> 1) & 7;
#pragma unroll
        for (int tt = 0; tt < CHUNK; tt++) {
            if (t0 == tt) { r[tt].x += s0 * v0.x; r[tt].y += s0 * v0.y; r[tt].z += s0 * v0.z; r[tt].w += s0 * v0.w; }
            if (t1 == tt) { r[tt].x += s1 * v1.x; r[tt].y += s1 * v1.y; r[tt].z += s1 * v1.z; r[tt].w += s1 * v1.w; }
            if (t2 == tt) { r[tt].x += s2 * v2.x; r[tt].y += s2 * v2.y; r[tt].z += s2 * v2.z; r[tt].w += s2 * v2.w; }
            if (t3 == tt) { r[tt].x += s3 * v3.x; r[tt].y += s3 * v3.y; r[tt].z += s3 * v3.z; r[tt].w += s3 * v3.w; }
        }
    }
    for (; j < nev; j++) {
        int e0 = sev[j];
        float4 v0 = emb4[(e0 >> 4) * F4 + f4];
        float s0 = 1.f - 2.f * (float)(e0 & 1);
        int t0 = (e0 >> 1) & 7;
#pragma unroll
        for (int tt = 0; tt < CHUNK; tt++)
            if (t0 == tt) { r[tt].x += s0 * v0.x; r[tt].y += s0 * v0.y; r[tt].z += s0 * v0.z; r[tt].w += s0 * v0.w; }
    }

    // exclusive chunk prefix for this thread's 4 features (4 scalar L2 hits)
    int f = f4 * 4;
    float4 acc;
    acc.x = g_Pt[(f + 0) * NCHUNK + c];
    acc.y = g_Pt[(f + 1) * NCHUNK + c];
    acc.z = g_Pt[(f + 2) * NCHUNK + c];
    acc.w = g_Pt[(f + 3) * NCHUNK + c];

    float4* ob = out4 + c * CHUNK * F4 + f4;
#pragma unroll
    for (int t = 0; t < CHUNK; t++) {
        acc.x += r[t].x; acc.y += r[t].y; acc.z += r[t].z; acc.w += r[t].w;
        ob[t * F4] = acc;                     // coalesced ST.128
    }
}

// ---------------------------------------------------------------------------
// Inputs (metadata order): embedding f32 [8192*256], node_span_starts i32
// [8192], node_span_ends i32 [8192], num_nodes i32 [1]. Output f32 [8192*256].
// ---------------------------------------------------------------------------
extern "C" void kernel_launch(void* const* d_in, const int* in_sizes, int n_in,
                              void* d_out, int out_size) {
    const float4* emb4   = (const float4*)d_in[0];
    const int*    starts = (const int*)d_in[1];
    const int*    ends   = (const int*)d_in[2];
    const int*    nn     = (const int*)d_in[3];
    float4*       out4   = (float4*)d_out;

    k_ev  <<<N_MAX / 256, 256>>>(starts, ends, nn);
    k_S   <<<NCHUNK, F4>>>(emb4);
    k_scan<<<FDIM, NCHUNK>>>();
    k_out <<<NCHUNK, F4>>>(emb4, out4);
}